// round 1
// baseline (speedup 1.0000x reference)
#include <cuda_runtime.h>
#include <math_constants.h>

#define BM 64
#define BN 64
#define DHEAD 128
#define QSTRIDE (DHEAD + 4)   // 132 floats: row stride for Q/K/V tiles (bank stagger)
#define PSTRIDE (BN + 4)      // 68 floats: row stride for P tile
#define NTHREADS 256

// warp-level reduction across the 16-lane tx group (xor masks < 16 stay in-half)
__device__ __forceinline__ float redmax16(float v) {
    v = fmaxf(v, __shfl_xor_sync(0xffffffffu, v, 1));
    v = fmaxf(v, __shfl_xor_sync(0xffffffffu, v, 2));
    v = fmaxf(v, __shfl_xor_sync(0xffffffffu, v, 4));
    v = fmaxf(v, __shfl_xor_sync(0xffffffffu, v, 8));
    return v;
}
__device__ __forceinline__ float redsum16(float v) {
    v += __shfl_xor_sync(0xffffffffu, v, 1);
    v += __shfl_xor_sync(0xffffffffu, v, 2);
    v += __shfl_xor_sync(0xffffffffu, v, 4);
    v += __shfl_xor_sync(0xffffffffu, v, 8);
    return v;
}

__global__ __launch_bounds__(NTHREADS, 1)
void flash_attn_fp32(const float* __restrict__ Q,
                     const float* __restrict__ K,
                     const float* __restrict__ V,
                     float* __restrict__ O,
                     int M)
{
    extern __shared__ float smem[];
    float* Qs = smem;                       // BM x QSTRIDE
    float* Ks = Qs + BM * QSTRIDE;          // BN x QSTRIDE
    float* Vs = Ks + BN * QSTRIDE;          // BN x QSTRIDE
    float* Ps = Vs + BN * QSTRIDE;          // BM x PSTRIDE

    const int tid = threadIdx.x;
    const int tx  = tid & 15;               // 16 col-threads
    const int ty  = tid >> 4;               // 16 row-threads
    const int row0 = blockIdx.x * BM;

    // ---- load Q tile (64x128) : 2048 float4, 8 per thread, fully coalesced ----
    {
        const float4* Qg = (const float4*)(Q + (size_t)row0 * DHEAD);
        #pragma unroll
        for (int p = 0; p < 8; p++) {
            int f = tid + p * NTHREADS;
            int r = f >> 5;                 // 32 float4 per row
            int c = f & 31;
            *(float4*)&Qs[r * QSTRIDE + c * 4] = Qg[r * 32 + c];
        }
    }

    // per-thread state: rows ty*4+i ; O cols {tx*4..tx*4+3, 64+tx*4..64+tx*4+3}
    float m_i[4], l_i[4];
    float o_acc[4][8];
    #pragma unroll
    for (int i = 0; i < 4; i++) {
        m_i[i] = -CUDART_INF_F;
        l_i[i] = 0.f;
        #pragma unroll
        for (int c = 0; c < 8; c++) o_acc[i][c] = 0.f;
    }

    const float scaling = 1.0f / 128.0f;    // module uses 1/d_k

    for (int kv0 = 0; kv0 < M; kv0 += BN) {
        __syncthreads();   // protect Ks/Vs/Ps from prior iteration's readers

        // ---- load K,V tiles (each 64x128) ----
        {
            const float4* Kg = (const float4*)(K + (size_t)kv0 * DHEAD);
            const float4* Vg = (const float4*)(V + (size_t)kv0 * DHEAD);
            #pragma unroll
            for (int p = 0; p < 8; p++) {
                int f = tid + p * NTHREADS;
                int r = f >> 5;
                int c = f & 31;
                *(float4*)&Ks[r * QSTRIDE + c * 4] = Kg[r * 32 + c];
                *(float4*)&Vs[r * QSTRIDE + c * 4] = Vg[r * 32 + c];
            }
        }
        __syncthreads();

        // ---- S = Q K^T : rows r_i = ty*4+i, cols c_j = tx + 16*j ----
        float s[4][4];
        #pragma unroll
        for (int i = 0; i < 4; i++)
            #pragma unroll
            for (int j = 0; j < 4; j++) s[i][j] = 0.f;

        #pragma unroll 8
        for (int k = 0; k < DHEAD; k += 4) {
            float4 qv[4], kv[4];
            #pragma unroll
            for (int i = 0; i < 4; i++)
                qv[i] = *(const float4*)&Qs[(ty * 4 + i) * QSTRIDE + k];
            #pragma unroll
            for (int j = 0; j < 4; j++)
                kv[j] = *(const float4*)&Ks[(tx + 16 * j) * QSTRIDE + k];
            #pragma unroll
            for (int i = 0; i < 4; i++)
                #pragma unroll
                for (int j = 0; j < 4; j++) {
                    s[i][j] += qv[i].x * kv[j].x;
                    s[i][j] += qv[i].y * kv[j].y;
                    s[i][j] += qv[i].z * kv[j].z;
                    s[i][j] += qv[i].w * kv[j].w;
                }
        }

        // ---- online softmax update ----
        #pragma unroll
        for (int i = 0; i < 4; i++) {
            float rmax = s[i][0];
            #pragma unroll
            for (int j = 1; j < 4; j++) rmax = fmaxf(rmax, s[i][j]);
            rmax = redmax16(rmax) * scaling;

            float m_new = fmaxf(m_i[i], rmax);
            float alpha = __expf(m_i[i] - m_new);
            m_i[i] = m_new;

            float rsum = 0.f;
            float p[4];
            #pragma unroll
            for (int j = 0; j < 4; j++) {
                p[j] = __expf(s[i][j] * scaling - m_new);
                rsum += p[j];
            }
            rsum = redsum16(rsum);
            l_i[i] = l_i[i] * alpha + rsum;

            #pragma unroll
            for (int c = 0; c < 8; c++) o_acc[i][c] *= alpha;

            #pragma unroll
            for (int j = 0; j < 4; j++)
                Ps[(ty * 4 + i) * PSTRIDE + tx + 16 * j] = p[j];
        }
        __syncthreads();   // P visible to everyone before PV

        // ---- O += P(64x64) @ V(64x128) ----
        #pragma unroll 4
        for (int j = 0; j < BN; j += 4) {
            float4 pr[4];
            #pragma unroll
            for (int i = 0; i < 4; i++)
                pr[i] = *(const float4*)&Ps[(ty * 4 + i) * PSTRIDE + j];

            #pragma unroll
            for (int jj = 0; jj < 4; jj++) {
                float4 v0 = *(const float4*)&Vs[(j + jj) * QSTRIDE + tx * 4];
                float4 v1 = *(const float4*)&Vs[(j + jj) * QSTRIDE + 64 + tx * 4];
                #pragma unroll
                for (int i = 0; i < 4; i++) {
                    float pij = (jj == 0) ? pr[i].x : (jj == 1) ? pr[i].y
                              : (jj == 2) ? pr[i].z : pr[i].w;
                    o_acc[i][0] += pij * v0.x;
                    o_acc[i][1] += pij * v0.y;
                    o_acc[i][2] += pij * v0.z;
                    o_acc[i][3] += pij * v0.w;
                    o_acc[i][4] += pij * v1.x;
                    o_acc[i][5] += pij * v1.y;
                    o_acc[i][6] += pij * v1.z;
                    o_acc[i][7] += pij * v1.w;
                }
            }
        }
    }

    // ---- epilogue: normalize and store ----
    #pragma unroll
    for (int i = 0; i < 4; i++) {
        float inv = 1.0f / l_i[i];
        float4 out0, out1;
        out0.x = o_acc[i][0] * inv; out0.y = o_acc[i][1] * inv;
        out0.z = o_acc[i][2] * inv; out0.w = o_acc[i][3] * inv;
        out1.x = o_acc[i][4] * inv; out1.y = o_acc[i][5] * inv;
        out1.z = o_acc[i][6] * inv; out1.w = o_acc[i][7] * inv;
        size_t rbase = (size_t)(row0 + ty * 4 + i) * DHEAD;
        *(float4*)&O[rbase + tx * 4]      = out0;
        *(float4*)&O[rbase + 64 + tx * 4] = out1;
    }
}

extern "C" void kernel_launch(void* const* d_in, const int* in_sizes, int n_in,
                              void* d_out, int out_size)
{
    const float* Q = (const float*)d_in[0];
    const float* K = (const float*)d_in[1];
    const float* V = (const float*)d_in[2];
    float* O = (float*)d_out;

    int N = in_sizes[0] / DHEAD;   // 8192 query rows
    int M = in_sizes[1] / DHEAD;   // 8192 keys

    size_t smem_bytes = (size_t)(BM * QSTRIDE + 2 * BN * QSTRIDE + BM * PSTRIDE) * sizeof(float);
    cudaFuncSetAttribute(flash_attn_fp32,
                         cudaFuncAttributeMaxDynamicSharedMemorySize,
                         (int)smem_bytes);

    flash_attn_fp32<<<N / BM, NTHREADS, smem_bytes>>>(Q, K, V, O, M);
}